// round 13
// baseline (speedup 1.0000x reference)
#include <cuda_runtime.h>
#include <math.h>

// ---------------------------------------------------------------------------
// MenuLoss: fused loss over y_pred/y (512,7,16,64,2) + Chebyshev coeffs (447).
//
//   K1 menu_lut : Chebyshev LUT at the 223 integer ids (mask∘round_ste is the
//                 identity on integers <= 222 in fp32). Coeffs staged in smem
//                 so the serial 447-chain isn't gated on global-load latency.
//   K2 menu_main: 1 block per HALF batch row (grid=1024 for wave balance).
//                 Packed f32x2 Clenshaw for the true-id Chebyshev evals
//                 (1 packed FMA-slot / elem / coeff), LUT gather for the pred
//                 path, tanh penalties, block reduce -> per-unit partials.
//   K3 menu_fin : deterministic combine of 2 halves per batch, diff^2, mean.
// ---------------------------------------------------------------------------

#define N_COEFFS 447
#define INNER    7168          // 7*16*64
#define HALF     3584
#define TPB      256

__device__ float  g_lut[224];
__device__ float4 g_part[8192];   // (pen, pred, true, 0) per half-row unit

// ---- packed f32x2 helpers (sm_100+) ---------------------------------------
__device__ __forceinline__ unsigned long long pack2f(float lo, float hi) {
    unsigned long long r;
    asm("mov.b64 %0, {%1, %2};" : "=l"(r) : "f"(lo), "f"(hi));
    return r;
}
__device__ __forceinline__ void unpack2f(unsigned long long v, float& lo, float& hi) {
    asm("mov.b64 {%0, %1}, %2;" : "=f"(lo), "=f"(hi) : "l"(v));
}
__device__ __forceinline__ unsigned long long fma2(unsigned long long a,
                                                   unsigned long long b,
                                                   unsigned long long c) {
    unsigned long long d;
    asm("fma.rn.f32x2 %0, %1, %2, %3;" : "=l"(d) : "l"(a), "l"(b), "l"(c));
    return d;
}

__device__ __forceinline__ float warp_sum(float v) {
    #pragma unroll
    for (int o = 16; o > 0; o >>= 1) v += __shfl_xor_sync(0xffffffffu, v, o);
    return v;
}

// ---- K1: LUT at integer ids, mimicking the reference forward recurrence ----
__global__ void menu_lut(const float* __restrict__ coeffs) {
    __shared__ float sc[N_COEFFS];
    int tid = threadIdx.x;
    for (int i = tid; i < N_COEFFS; i += 256) sc[i] = coeffs[i];
    __syncthreads();
    int k = tid;
    if (k <= 222) {
        float xn  = (float)k / 111.0f - 1.0f;
        float Tm1 = 1.0f;
        float Tn  = xn;
        float acc = sc[0] + sc[1] * xn;
        float tx  = 2.0f * xn;
        #pragma unroll 5
        for (int i = 2; i < N_COEFFS; ++i) {
            float Tnew = tx * Tn - Tm1;
            acc += sc[i] * Tnew;
            Tm1 = Tn; Tn = Tnew;
        }
        g_lut[k] = acc;
    }
}

// ---- chunk worker: 2*NC elements, NC packed Clenshaw chains ----------------
template<int NC>
__device__ __forceinline__ void process_chunk(
    int tid, int jbase,
    const float2* __restrict__ p2, const float2* __restrict__ t2,
    const unsigned long long* __restrict__ sc, const float* __restrict__ slut,
    float& zacc, float& racc, float& pacc, float& tacc)
{
    float amt[2 * NC];
    unsigned long long twox[NC], b1[NC], b2[NC];

    #pragma unroll
    for (int i = 0; i < NC; ++i) {
        float xlo = 0.f, xhi = 0.f;
        #pragma unroll
        for (int h = 0; h < 2; ++h) {
            int s = 2 * i + h;
            int e = tid + (jbase + s) * TPB;
            float2 tv = t2[e];
            float2 pv = p2[e];
            float xn = tv.x / 111.0f - 1.0f;
            if (h == 0) xlo = xn; else xhi = xn;
            amt[s] = tv.y;
            // penalties on the pred side
            float a = tanhf(4.0f * pv.x);          // 1 - id_zero_mask
            float m = tanhf(4.0f * pv.y);          // amount_nonzero_mask
            zacc += (a + m) - 2.0f * a * m;        // case1 + case2
            racc += fmaxf(pv.x - 222.0f, 0.0f);    // relu(id - HIGHEST_ID)
            // pred calories via LUT (mask(round(id)) == round(id) exactly)
            int idx = (int)rintf(pv.x);
            idx = idx < 0 ? 0 : (idx > 222 ? 222 : idx);
            pacc = fmaf(slut[idx], pv.y, pacc);
        }
        twox[i] = pack2f(2.0f * xlo, 2.0f * xhi);
        b1[i] = 0ull;
        b2[i] = 0ull;
    }

    const unsigned long long NEG1 = pack2f(-1.0f, -1.0f);
    // Clenshaw: b_k = c_k + 2x*b_{k+1} - b_{k+2}, k = 446 .. 1
    #pragma unroll 2
    for (int k = N_COEFFS - 1; k >= 1; --k) {
        unsigned long long c2 = sc[k];
        #pragma unroll
        for (int i = 0; i < NC; ++i) {
            unsigned long long tmp = fma2(NEG1, b2[i], c2);      // c - b2
            unsigned long long bn  = fma2(twox[i], b1[i], tmp);  // + 2x*b1
            b2[i] = b1[i];
            b1[i] = bn;
        }
    }

    float c0, c0h;
    unpack2f(sc[0], c0, c0h);
    #pragma unroll
    for (int i = 0; i < NC; ++i) {
        float t0, t1, u0, u1, x0, x1;
        unpack2f(b1[i], t0, t1);
        unpack2f(b2[i], u0, u1);
        unpack2f(twox[i], x0, x1);
        float r0 = fmaf(0.5f * x0, t0, c0 - u0);  // result = c0 + x*b1 - b2
        float r1 = fmaf(0.5f * x1, t1, c0 - u1);
        tacc = fmaf(r0, amt[2 * i],     tacc);
        tacc = fmaf(r1, amt[2 * i + 1], tacc);
    }
}

// ---- K2: main, 1 block per half-row unit ----------------------------------
__global__ void __launch_bounds__(TPB, 4) menu_main(
    const float* __restrict__ y_pred,
    const float* __restrict__ y,
    const float* __restrict__ coeffs)
{
    __shared__ unsigned long long sc[N_COEFFS];  // coeff broadcast into both lanes
    __shared__ float slut[224];
    __shared__ float sw0[8], sw1[8], sw2[8];

    int tid = threadIdx.x;
    for (int i = tid; i < N_COEFFS; i += TPB) {
        float c = coeffs[i];
        sc[i] = pack2f(c, c);
    }
    if (tid < 223) slut[tid] = g_lut[tid];
    __syncthreads();

    int u = blockIdx.x;
    size_t base = (size_t)(u >> 1) * INNER + (size_t)(u & 1) * HALF;
    const float2* p2 = reinterpret_cast<const float2*>(y_pred) + base;
    const float2* t2 = reinterpret_cast<const float2*>(y)      + base;

    float z = 0.f, r = 0.f, p = 0.f, t = 0.f;
    // 3584 elems / 256 threads = 14 per thread: chunks {8, 6}
    process_chunk<4>(tid, 0, p2, t2, sc, slut, z, r, p, t);
    process_chunk<3>(tid, 8, p2, t2, sc, slut, z, r, p, t);

    float pen = z + r;
    pen = warp_sum(pen);
    p   = warp_sum(p);
    t   = warp_sum(t);

    int lane = tid & 31, w = tid >> 5;
    if (lane == 0) { sw0[w] = pen; sw1[w] = p; sw2[w] = t; }
    __syncthreads();
    if (w == 0) {
        float a = (lane < 8) ? sw0[lane] : 0.f;
        float q = (lane < 8) ? sw1[lane] : 0.f;
        float s = (lane < 8) ? sw2[lane] : 0.f;
        a = warp_sum(a); q = warp_sum(q); s = warp_sum(s);
        if (lane == 0) g_part[u] = make_float4(a, q, s, 0.f);
    }
}

// ---- K3: finalize ---------------------------------------------------------
__global__ void menu_fin(float* __restrict__ out, int B) {
    __shared__ float sred[16];
    int tid = threadIdx.x;
    float v = 0.f;
    for (int b = tid; b < B; b += 512) {
        float4 g0 = g_part[2 * b];
        float4 g1 = g_part[2 * b + 1];
        float pen  = g0.x + g1.x;
        float pred = (g0.y + g1.y) * (1.0f / 700.0f);
        float tru  = (g0.z + g1.z) * (1.0f / 700.0f);
        float d = tru - pred;
        v += pen + d * d;
    }
    v = warp_sum(v);
    int lane = tid & 31, w = tid >> 5;
    if (lane == 0) sred[w] = v;
    __syncthreads();
    if (w == 0) {
        float x = (lane < 16) ? sred[lane] : 0.f;
        x = warp_sum(x);
        if (lane == 0) out[0] = x / (float)B;
    }
}

// ---------------------------------------------------------------------------
extern "C" void kernel_launch(void* const* d_in, const int* in_sizes, int n_in,
                              void* d_out, int out_size) {
    const float* y_pred = (const float*)d_in[0];
    const float* y      = (const float*)d_in[1];
    const float* coeffs = (const float*)d_in[2];

    int B = in_sizes[0] / (2 * INNER);
    if (B < 1) B = 1;
    if (B > 4096) B = 4096;

    menu_lut<<<1, 256>>>(coeffs);
    menu_main<<<2 * B, TPB>>>(y_pred, y, coeffs);
    menu_fin<<<1, 512>>>((float*)d_out, B);
}

// round 14
// speedup vs baseline: 6.1354x; 6.1354x over previous
#include <cuda_runtime.h>
#include <math.h>

// ---------------------------------------------------------------------------
// MenuLoss via dense-table reconstruction.
//
// f(x) = sum_k c_k T_k(x/111-1) = sum_k c_k cos(k*theta), theta = acos(xn):
// band-limited (max freq 446) in theta -> tabulate on uniform theta grid
// (N=6144 intervals over [0,pi]) and reconstruct with Catmull-Rom cubic.
// Relative attenuation ~ (446*pi/N)^4/30 ~ 1e-4, oscillatory (unbiased).
//
//   K1 menu_build: blocks 0..24 -> theta-table (Clenshaw per node),
//                  block 25     -> integer-id LUT for the pred path
//                  (mask(round_ste(id)) == rint(id) exactly for id in [0,222]).
//   K2 menu_main : 1 block per half batch row (grid=1024, 8 CTAs/SM, 1 wave).
//                  Per element: fast acos + cubic table gather (true path),
//                  LUT gather (pred path), MUFU tanh penalties, block reduce.
//   K3 menu_fin  : deterministic combine of 2 halves/batch, diff^2, mean.
// ---------------------------------------------------------------------------

#define N_COEFFS 447
#define INNER    7168          // 7*16*64
#define HALF     3584
#define TPB      256
#define TABN     6144          // intervals over [0, pi]
#define TABSZ    6148          // nodes j = -1 .. TABN+1 (+1 pad, /4 aligned)

__device__ float  g_table[TABSZ];
__device__ float  g_lut[224];
__device__ float4 g_part[8192];   // (pen, pred, true, 0) per half-row unit

__device__ __forceinline__ float warp_sum(float v) {
    #pragma unroll
    for (int o = 16; o > 0; o >>= 1) v += __shfl_xor_sync(0xffffffffu, v, o);
    return v;
}

__device__ __forceinline__ float tanh_fast(float x) {
    float y;
    asm("tanh.approx.f32 %0, %1;" : "=f"(y) : "f"(x));
    return y;
}

// acos via A&S 4.4.45: acos(x) = sqrt(1-x)*P(x) for x>=0, pi - acos(-x) else.
// |poly err| ~2e-8 rad; fp32 eval ~1e-7 rad.
__device__ __forceinline__ float acos_fast(float x) {
    float ax = fabsf(x);
    float s;
    asm("sqrt.approx.f32 %0, %1;" : "=f"(s) : "f"(1.0f - ax));
    float p = -0.0012624911f;
    p = fmaf(p, ax,  0.0066700901f);
    p = fmaf(p, ax, -0.0170881256f);
    p = fmaf(p, ax,  0.0308918810f);
    p = fmaf(p, ax, -0.0501743046f);
    p = fmaf(p, ax,  0.0889789874f);
    p = fmaf(p, ax, -0.2145988016f);
    p = fmaf(p, ax,  1.5707963050f);
    float r = s * p;
    return (x >= 0.0f) ? r : (3.14159265358979f - r);
}

// ---- K1: table + LUT build -------------------------------------------------
__global__ void menu_build(const float* __restrict__ coeffs) {
    __shared__ float sc[N_COEFFS];
    int tid = threadIdx.x;
    for (int i = tid; i < N_COEFFS; i += TPB) sc[i] = coeffs[i];
    __syncthreads();

    if (blockIdx.x < 25) {
        // theta-grid nodes: table slot j holds f at theta = (j-1)*pi/TABN.
        // f(theta) = sum c_k cos(k theta) = Cheb(cos(theta)) -- the even,
        // periodic extension is exact, so j=-1 and j=TABN+1 are analytic.
        int j = blockIdx.x * TPB + tid;
        if (j < TABN + 3) {
            float th = (float)(j - 1) * (3.14159265358979323846f / (float)TABN);
            float xn = cosf(th);
            // Clenshaw: b_k = c_k + 2x b_{k+1} - b_{k+2}
            float tx = 2.0f * xn;
            float b1 = 0.0f, b2 = 0.0f;
            #pragma unroll 2
            for (int k = N_COEFFS - 1; k >= 1; --k) {
                float bn = fmaf(tx, b1, sc[k] - b2);
                b2 = b1; b1 = bn;
            }
            g_table[j] = fmaf(xn, b1, sc[0] - b2);
        }
    } else {
        // integer-id LUT, forward recurrence (matches reference ordering)
        int k = tid;
        if (k <= 222) {
            float xn  = (float)k / 111.0f - 1.0f;
            float Tm1 = 1.0f;
            float Tn  = xn;
            float acc = sc[0] + sc[1] * xn;
            float tx  = 2.0f * xn;
            #pragma unroll 5
            for (int i = 2; i < N_COEFFS; ++i) {
                float Tnew = fmaf(tx, Tn, -Tm1);
                acc = fmaf(sc[i], Tnew, acc);
                Tm1 = Tn; Tn = Tnew;
            }
            g_lut[k] = acc;
        }
    }
}

// ---- K2: main, 1 block per half-row unit ----------------------------------
__global__ void __launch_bounds__(TPB, 8) menu_main(
    const float* __restrict__ y_pred,
    const float* __restrict__ y)
{
    __shared__ float stab[TABSZ];
    __shared__ float slut[224];
    __shared__ float sw0[8], sw1[8], sw2[8];

    int tid = threadIdx.x;
    // stage table (float4 loads) + lut
    {
        const float4* src = reinterpret_cast<const float4*>(g_table);
        float4* dst = reinterpret_cast<float4*>(stab);
        #pragma unroll
        for (int i = tid; i < TABSZ / 4; i += TPB) dst[i] = src[i];
        if (tid < 224) slut[tid] = g_lut[tid];
    }
    __syncthreads();

    int u = blockIdx.x;
    size_t base = (size_t)(u >> 1) * INNER + (size_t)(u & 1) * HALF;
    const float2* p2 = reinterpret_cast<const float2*>(y_pred) + base;
    const float2* t2 = reinterpret_cast<const float2*>(y)      + base;

    const float TSCALE = (float)TABN / 3.14159265358979323846f;

    float z = 0.f, r = 0.f, p = 0.f, t = 0.f;
    #pragma unroll 2
    for (int s = 0; s < HALF / TPB; ++s) {
        int e = tid + s * TPB;
        float2 tv = t2[e];
        float2 pv = p2[e];

        // ---- penalties (pred side) ----
        float a = tanh_fast(4.0f * pv.x);        // 1 - id_zero_mask
        float m = tanh_fast(4.0f * pv.y);        // amount_nonzero_mask
        z += (a + m) - 2.0f * a * m;             // case1 + case2
        r += fmaxf(pv.x - 222.0f, 0.0f);

        // ---- pred calories via integer LUT ----
        int pidx = (int)rintf(pv.x);
        pidx = pidx < 0 ? 0 : (pidx > 222 ? 222 : pidx);
        p = fmaf(slut[pidx], pv.y, p);

        // ---- true calories via theta-table cubic ----
        float xn = fmaf(tv.x, 1.0f / 111.0f, -1.0f);
        xn = fminf(fmaxf(xn, -1.0f), 1.0f);
        float th = acos_fast(xn);
        float tt = th * TSCALE;
        int   i  = (int)tt;
        i = i < 0 ? 0 : (i > TABN - 1 ? TABN - 1 : i);
        float fr = tt - (float)i;
        float y0 = stab[i];
        float y1 = stab[i + 1];
        float y2 = stab[i + 2];
        float y3 = stab[i + 3];
        // Catmull-Rom
        float c1 = 0.5f * (y2 - y0);
        float c2 = fmaf(2.0f, y0, fmaf(-5.0f, y1, fmaf(4.0f, y2, -y3))) * 0.5f;
        float c3 = fmaf(3.0f, y1 - y2, y3 - y0) * 0.5f;
        float val = fmaf(fmaf(fmaf(c3, fr, c2), fr, c1), fr, y1);
        t = fmaf(val, tv.y, t);
    }

    float pen = z + r;
    pen = warp_sum(pen);
    p   = warp_sum(p);
    t   = warp_sum(t);

    int lane = tid & 31, w = tid >> 5;
    if (lane == 0) { sw0[w] = pen; sw1[w] = p; sw2[w] = t; }
    __syncthreads();
    if (w == 0) {
        float aa = (lane < 8) ? sw0[lane] : 0.f;
        float qq = (lane < 8) ? sw1[lane] : 0.f;
        float ss = (lane < 8) ? sw2[lane] : 0.f;
        aa = warp_sum(aa); qq = warp_sum(qq); ss = warp_sum(ss);
        if (lane == 0) g_part[u] = make_float4(aa, qq, ss, 0.f);
    }
}

// ---- K3: finalize ---------------------------------------------------------
__global__ void menu_fin(float* __restrict__ out, int B) {
    __shared__ float sred[16];
    int tid = threadIdx.x;
    float v = 0.f;
    for (int b = tid; b < B; b += 512) {
        float4 g0 = g_part[2 * b];
        float4 g1 = g_part[2 * b + 1];
        float pen  = g0.x + g1.x;
        float pred = (g0.y + g1.y) * (1.0f / 700.0f);
        float tru  = (g0.z + g1.z) * (1.0f / 700.0f);
        float d = tru - pred;
        v += pen + d * d;
    }
    v = warp_sum(v);
    int lane = tid & 31, w = tid >> 5;
    if (lane == 0) sred[w] = v;
    __syncthreads();
    if (w == 0) {
        float x = (lane < 16) ? sred[lane] : 0.f;
        x = warp_sum(x);
        if (lane == 0) out[0] = x / (float)B;
    }
}

// ---------------------------------------------------------------------------
extern "C" void kernel_launch(void* const* d_in, const int* in_sizes, int n_in,
                              void* d_out, int out_size) {
    const float* y_pred = (const float*)d_in[0];
    const float* y      = (const float*)d_in[1];
    const float* coeffs = (const float*)d_in[2];

    int B = in_sizes[0] / (2 * INNER);
    if (B < 1) B = 1;
    if (B > 4096) B = 4096;

    menu_build<<<26, TPB>>>(coeffs);
    menu_main<<<2 * B, TPB>>>(y_pred, y);
    menu_fin<<<1, 512>>>((float*)d_out, B);
}